// round 8
// baseline (speedup 1.0000x reference)
#include <cuda_runtime.h>
#include <cstdint>

// ---------------- config ----------------
#define GRID  444              // 3 x 148, resident with (256,3)
#define WPB   8                // warps per block
#define TW    (GRID * WPB)     // total warps = 3552
#define NBUF  3                // triple buffer -> 2 cp.async groups in flight
#define SMEM_DYN (NBUF * WPB * 168 * 16)   // 64512 B tile storage

// ---------------- device scratch ----------------
__device__ float    g_part[GRID * 8];    // [blk][0..3]=S, [4..7]=Q
__device__ float    g_scale[8];
__device__ unsigned g_cnt  = 0;
__device__ unsigned g_flag = 0;

__device__ __forceinline__ void cp16(float4* dst_smem, const float4* src_gmem) {
    unsigned d = (unsigned)__cvta_generic_to_shared(dst_smem);
    asm volatile("cp.async.cg.shared.global [%0], [%1], 16;\n"
                 :: "r"(d), "l"(src_gmem));
}

struct cf { float re, im; };
__device__ __forceinline__ cf cmul(cf a, cf b) { return {a.re*b.re - a.im*b.im, a.re*b.im + a.im*b.re}; }
__device__ __forceinline__ cf cadd(cf a, cf b) { return {a.re + b.re, a.im + b.im}; }

__global__ __launch_bounds__(256, 3) void k_all(
    const float* __restrict__ x, const float* __restrict__ W,
    const float* __restrict__ b, const float* __restrict__ vp,
    const float* __restrict__ gamma, const float* __restrict__ beta,
    float* __restrict__ out, int B)
{
    extern __shared__ float4 smv[];        // [NBUF][WPB][168]
    __shared__ float2 sU[256];             // sU[j*16+p] = U[p][j] * (-i)^popc(j)
    __shared__ float  sPart[WPB][8];
    __shared__ float  sScale[8];
    __shared__ unsigned sTicket;

    const int tid  = threadIdx.x;
    const int w    = tid >> 5;
    const int lane = tid & 31;
    const int hh   = lane >> 4;            // half role
    const int q    = lane & 15;            // basis index
    const int bid  = blockIdx.x;

    const unsigned epoch = *(volatile unsigned*)&g_flag;

    const float4* xv = reinterpret_cast<const float4*>(x);
    const int wg = bid * WPB + w;          // global warp id

    auto issue = [&](int s, int buf) {     // stage sample s (rows 0..23)
        const float4* src = xv + (long)s * 196;
        float4* dst = &smv[(buf*WPB + w) * 168];
        #pragma unroll
        for (int k = 0; k < 5; k++) cp16(dst + k*32 + lane, src + k*32 + lane);
        if (lane < 8) cp16(dst + 160 + lane, src + 160 + lane);
        asm volatile("cp.async.commit_group;\n");
    };

    // ---- prologue: 2 groups in flight ----
    if (wg < B) issue(wg, 0);
    if (wg + TW < B) issue(wg + TW, 1);

    // ---- warp 0 builds (pre-rotated) U while prologue loads fly ----
    if (tid < 16) {
        const int j = tid;                 // column
        cf st[16];
        #pragma unroll
        for (int i = 0; i < 16; i++) st[i] = { (i == j) ? 1.0f : 0.0f, 0.0f };
        for (int l = 0; l < 3; l++) {
            for (int ww = 0; ww < 4; ww++) {
                float tx = vp[(l*4 + ww)*3 + 0];
                float ty = vp[(l*4 + ww)*3 + 1];
                float tz = vp[(l*4 + ww)*3 + 2];
                float cx, sx, cy, sy, cz, sz;
                sincosf(tx*0.5f, &sx, &cx);
                sincosf(ty*0.5f, &sy, &cy);
                sincosf(tz*0.5f, &sz, &cz);
                cf M00{ cy*cx,  sy*sx }, M01{ -sy*cx, -cy*sx };
                cf M10{ sy*cx, -cy*sx }, M11{  cy*cx, -sy*sx };
                cf e0{ cz, -sz }, e1{ cz, sz };
                cf G00 = cmul(e0, M00), G01 = cmul(e0, M01);
                cf G10 = cmul(e1, M10), G11 = cmul(e1, M11);
                int mask = 8 >> ww;
                #pragma unroll
                for (int i = 0; i < 16; i++) {
                    if (i & mask) continue;
                    cf a0 = st[i], a1 = st[i | mask];
                    st[i]        = cadd(cmul(G00, a0), cmul(G01, a1));
                    st[i | mask] = cadd(cmul(G10, a0), cmul(G11, a1));
                }
            }
            for (int ww = 0; ww < 3; ww++) {   // CNOT chain
                int cm = 8 >> ww, tm = 4 >> ww;
                cf tmp[16];
                #pragma unroll
                for (int i = 0; i < 16; i++) tmp[i] = st[(i & cm) ? (i ^ tm) : i];
                #pragma unroll
                for (int i = 0; i < 16; i++) st[i] = tmp[i];
            }
        }
        const int pm = __popc(j) & 3;          // bake in (-i)^popc(j)
        #pragma unroll
        for (int i = 0; i < 16; i++) {
            float r = st[i].re, im = st[i].im, nr, ni;
            if      (pm == 0) { nr =  r;  ni =  im; }
            else if (pm == 1) { nr =  im; ni = -r;  }
            else if (pm == 2) { nr = -r;  ni = -im; }
            else              { nr = -im; ni =  r;  }
            sU[j*16 + i] = make_float2(nr, ni);
        }
    }
    __syncthreads();

    // ---- per-lane constants: this half's 8 rotated-U terms for basis q ----
    float Ur[8], Ui[8];
    #pragma unroll
    for (int jj = 0; jj < 8; jj++) {
        float2 u = sU[(hh*8 + jj)*16 + q];
        Ur[jj] = u.x; Ui[jj] = u.y;
    }
    const float4 wrow = reinterpret_cast<const float4*>(W)[q];
    const float4 bv   = *reinterpret_cast<const float4*>(b);
    const float wA = hh ? wrow.z : wrow.x;     // half0 reduces f0,f1; half1 f2,f3
    const float wB = hh ? wrow.w : wrow.y;

    float runS0=0, runS1=0, runS2=0, runS3=0;
    float runQ0=0, runQ1=0, runQ2=0, runQ3=0;

    const int cb = q & 3, rb = q >> 2;
    const int poolOff = (rb*6 + hh*3)*28 + cb*6;   // this half's 3 rows

    int cur = 0;                                    // buffer holding sample s
    for (int s = wg; s < B; s += TW) {
        const long s2 = (long)s + 2L*TW;
        if (s2 < B) {
            int nb = cur - 1; if (nb < 0) nb += NBUF;   // (cur+2)%3
            issue((int)s2, nb);
            asm volatile("cp.async.wait_group 2;\n");
        } else if (s + TW < B) {
            asm volatile("cp.async.wait_group 1;\n");
        } else {
            asm volatile("cp.async.wait_group 0;\n");
        }
        __syncwarp();

        // ---- pooling: half sums its 3 rows x 6 cols of bin q ----
        const float* s0f = reinterpret_cast<const float*>(&smv[(cur*WPB + w)*168]) + poolOff;
        float2 acc = make_float2(0.f, 0.f);
        #pragma unroll
        for (int r = 0; r < 3; r++) {
            const float2* rp = reinterpret_cast<const float2*>(s0f + r*28);
            acc.x += rp[0].x + rp[1].x + rp[2].x;
            acc.y += rp[0].y + rp[1].y + rp[2].y;
        }
        float v = acc.x + acc.y;
        v += __shfl_xor_sync(0xffffffffu, v, 16);   // full pooled bin q (both halves)
        v *= (1.0f / 36.0f);

        // ---- feats: split-half butterfly (10 shfls total) ----
        float fa = v * wA, fb = v * wB;
        #pragma unroll
        for (int m = 1; m < 16; m <<= 1) {
            fa += __shfl_xor_sync(0xffffffffu, fa, m);
            fb += __shfl_xor_sync(0xffffffffu, fb, m);
        }
        float fc = __shfl_xor_sync(0xffffffffu, fa, 16);
        float fd = __shfl_xor_sync(0xffffffffu, fb, 16);
        // half0: fa=f0',fb=f1',fc=f2',fd=f3' ; half1: fa=f2',fb=f3',fc=f0',fd=f1'
        float f0 = (hh ? fc : fa) + bv.x;
        float f1 = (hh ? fd : fb) + bv.y;
        float f2 = (hh ? fa : fc) + bv.z;
        float f3 = (hh ? fb : fd) + bv.w;

        // ---- encoded product-state magnitudes ----
        float c0_,s_0,c1_,s_1,c2_,s_2,c3_,s_3;
        __sincosf(0.5f*f0, &s_0, &c0_);
        __sincosf(0.5f*f1, &s_1, &c1_);
        __sincosf(0.5f*f2, &s_2, &c2_);
        __sincosf(0.5f*f3, &s_3, &c3_);
        float w23[4] = { c2_*c3_, c2_*s_3, s_2*c3_, s_2*s_3 };
        float wa = hh ? (s_0*c1_) : (c0_*c1_);
        float wb = hh ? (s_0*s_1) : (c0_*s_1);

        // ---- amp partial over this half's 8 j-terms ----
        float ar = 0.f, ai = 0.f;
        #pragma unroll
        for (int jj = 0; jj < 8; jj++) {
            float m = ((jj < 4) ? wa : wb) * w23[jj & 3];
            ar += Ur[jj]*m;
            ai += Ui[jj]*m;
        }
        ar += __shfl_xor_sync(0xffffffffu, ar, 16);
        ai += __shfl_xor_sync(0xffffffffu, ai, 16);
        float prob = ar*ar + ai*ai;

        // ---- expZ: Walsh-Hadamard butterfly over 16-lane half ----
        float v4 = prob;
        #pragma unroll
        for (int m = 1; m < 16; m <<= 1) {
            float o = __shfl_xor_sync(0xffffffffu, v4, m);
            v4 = (q & m) ? (o - v4) : (v4 + o);
        }
        float z0 = __shfl_sync(0xffffffffu, v4, 8);
        float z1 = __shfl_sync(0xffffffffu, v4, 4);
        float z2 = __shfl_sync(0xffffffffu, v4, 2);
        float z3 = __shfl_sync(0xffffffffu, v4, 1);

        if (lane == 0) {
            reinterpret_cast<float4*>(out)[s] = make_float4(z0, z1, z2, z3);
            runS0 += z0; runS1 += z1; runS2 += z2; runS3 += z3;
            runQ0 += z0*z0; runQ1 += z1*z1; runQ2 += z2*z2; runQ3 += z3*z3;
        }
        cur++; if (cur == NBUF) cur = 0;
    }

    if (lane == 0) {
        sPart[w][0] = runS0; sPart[w][1] = runS1;
        sPart[w][2] = runS2; sPart[w][3] = runS3;
        sPart[w][4] = runQ0; sPart[w][5] = runQ1;
        sPart[w][6] = runQ2; sPart[w][7] = runQ3;
    }
    __syncthreads();

    if (tid < 8) {
        float t = 0.f;
        #pragma unroll
        for (int k = 0; k < WPB; k++) t += sPart[k][tid];
        g_part[bid * 8 + tid] = t;
    }
    __threadfence();
    if (tid == 0) sTicket = atomicAdd(&g_cnt, 1u);
    __syncthreads();

    if ((sTicket % GRID) == GRID - 1) {
        __threadfence();
        float* sRed = reinterpret_cast<float*>(sU);   // 512-float scratch
        {
            int ch = tid & 7, row = tid >> 3;          // 32 rows x 8 channels
            float s = 0.f;
            for (int p2 = row; p2 < GRID; p2 += 32) s += __ldcg(&g_part[p2*8 + ch]);
            sRed[row*8 + ch] = s;
        }
        __syncthreads();
        if (tid < 8) {
            float tt = 0.f;
            #pragma unroll
            for (int r = 0; r < 32; r++) tt += sRed[r*8 + tid];
            sRed[256 + tid] = tt;
        }
        __syncthreads();
        if (tid < 4) {
            float invB = 1.0f / (float)B;
            float mu  = sRed[256 + tid] * invB;
            float var = sRed[260 + tid] * invB - mu*mu;    // biased var
            float scw = gamma[tid] * rsqrtf(var + 1e-5f);
            g_scale[tid]     = scw;
            g_scale[4 + tid] = beta[tid] - mu * scw;
        }
        __threadfence();
        __syncthreads();
        if (tid == 0) atomicAdd(&g_flag, 1u);
    }

    if (tid == 0) {
        while (*(volatile unsigned*)&g_flag == epoch) __nanosleep(64);
    }
    __syncthreads();
    __threadfence();

    if (tid < 8) sScale[tid] = *(volatile float*)&g_scale[tid];
    __syncthreads();

    // ---- normalize: one f4 per thread, coalesced (444*256 >= B/1) ----
    {
        float4 scv = *reinterpret_cast<const float4*>(&sScale[0]);
        float4 shv = *reinterpret_cast<const float4*>(&sScale[4]);
        for (long i = (long)bid * 256 + tid; i < B; i += (long)GRID * 256) {
            float4 r = reinterpret_cast<float4*>(out)[i];
            r.x = r.x*scv.x + shv.x;
            r.y = r.y*scv.y + shv.y;
            r.z = r.z*scv.z + shv.z;
            r.w = r.w*scv.w + shv.w;
            reinterpret_cast<float4*>(out)[i] = r;
        }
    }
}

// ---------------- launch ----------------------------------------------------
extern "C" void kernel_launch(void* const* d_in, const int* in_sizes, int n_in,
                              void* d_out, int out_size)
{
    const float* x     = (const float*)d_in[0];  // [B,1,28,28]
    const float* W     = (const float*)d_in[1];  // [16,4]
    const float* b     = (const float*)d_in[2];  // [4]
    const float* vp    = (const float*)d_in[3];  // [3,4,3]
    const float* gamma = (const float*)d_in[4];  // [4]
    const float* beta  = (const float*)d_in[5];  // [4]
    float* out = (float*)d_out;                  // [B,4]

    int B = in_sizes[0] / 784;                   // 65536

    cudaFuncSetAttribute(k_all, cudaFuncAttributeMaxDynamicSharedMemorySize, SMEM_DYN);
    k_all<<<GRID, 256, SMEM_DYN>>>(x, W, b, vp, gamma, beta, out, B);
}

// round 9
// speedup vs baseline: 1.0842x; 1.0842x over previous
#include <cuda_runtime.h>
#include <cstdint>

// ---------------- config ----------------
#define GRID  444              // 3 x 148, resident with (256,3)
#define WPB   8                // warps per block
#define TW    (GRID * WPB)     // total warps = 3552
#define HOFF  100              // smem words per half-region (96 used + pad)

// ---------------- device scratch ----------------
__device__ float    g_part[GRID * 8];    // [blk][0..3]=S, [4..7]=Q
__device__ float    g_scale[8];
__device__ unsigned g_cnt  = 0;
__device__ unsigned g_flag = 0;

struct cf { float re, im; };
__device__ __forceinline__ cf cmul(cf a, cf b) { return {a.re*b.re - a.im*b.im, a.re*b.im + a.im*b.re}; }
__device__ __forceinline__ cf cadd(cf a, cf b) { return {a.re + b.re, a.im + b.im}; }

__global__ __launch_bounds__(256, 3) void k_all(
    const float* __restrict__ x, const float* __restrict__ W,
    const float* __restrict__ b, const float* __restrict__ vp,
    const float* __restrict__ gamma, const float* __restrict__ beta,
    float* __restrict__ out, int B)
{
    __shared__ float  sPool[WPB * 2 * HOFF];   // rowsum transpose, 6.4 KB
    __shared__ float4 sUf4[256];               // U'[p][j] packed by j-pairs, 4 KB
    __shared__ float  sPart[WPB][8];
    __shared__ float  sScale[8];
    __shared__ unsigned sTicket;

    const int tid  = threadIdx.x;
    const int w    = tid >> 5;
    const int lane = tid & 31;
    const int h    = lane >> 4;            // half = sample within pair
    const int q    = lane & 15;            // basis index / row-lane id
    const int bid  = blockIdx.x;

    const unsigned epoch = *(volatile unsigned*)&g_flag;

    const float4* xv = reinterpret_cast<const float4*>(x);
    const int wg = bid * WPB + w;          // global warp id
    const long STRIDE = 2L * TW;

    // per-lane load roles: row q (6 f4) + quarter-row of rows 16..23 (3 f4)
    const int rowB    = 16 + (q >> 1);
    const int f4offB  = (q & 1) * 3;

    float4 A0,A1,A2,A3,A4,A5, B0,B1,B2;
    auto ldall = [&](long s2) {
        const float4* pa = xv + (s2 + h) * 196 + q * 7;
        A0 = __ldcs(pa+0); A1 = __ldcs(pa+1); A2 = __ldcs(pa+2);
        A3 = __ldcs(pa+3); A4 = __ldcs(pa+4); A5 = __ldcs(pa+5);
        const float4* pb = xv + (s2 + h) * 196 + rowB * 7 + f4offB;
        B0 = __ldcs(pb+0); B1 = __ldcs(pb+1); B2 = __ldcs(pb+2);
    };

    long s2 = (long)wg * 2;
    ldall(s2);                             // prologue (always valid: 2*3551 < B)

    // ---- warp 0 builds pre-rotated U while prologue loads fly ----
    if (tid < 16) {
        const int j = tid;                 // column
        cf st[16];
        #pragma unroll
        for (int i = 0; i < 16; i++) st[i] = { (i == j) ? 1.0f : 0.0f, 0.0f };
        for (int l = 0; l < 3; l++) {
            for (int ww = 0; ww < 4; ww++) {
                float tx = vp[(l*4 + ww)*3 + 0];
                float ty = vp[(l*4 + ww)*3 + 1];
                float tz = vp[(l*4 + ww)*3 + 2];
                float cx, sx, cy, sy, cz, sz;
                sincosf(tx*0.5f, &sx, &cx);
                sincosf(ty*0.5f, &sy, &cy);
                sincosf(tz*0.5f, &sz, &cz);
                cf M00{ cy*cx,  sy*sx }, M01{ -sy*cx, -cy*sx };
                cf M10{ sy*cx, -cy*sx }, M11{  cy*cx, -sy*sx };
                cf e0{ cz, -sz }, e1{ cz, sz };
                cf G00 = cmul(e0, M00), G01 = cmul(e0, M01);
                cf G10 = cmul(e1, M10), G11 = cmul(e1, M11);
                int mask = 8 >> ww;
                #pragma unroll
                for (int i = 0; i < 16; i++) {
                    if (i & mask) continue;
                    cf a0 = st[i], a1 = st[i | mask];
                    st[i]        = cadd(cmul(G00, a0), cmul(G01, a1));
                    st[i | mask] = cadd(cmul(G10, a0), cmul(G11, a1));
                }
            }
            for (int ww = 0; ww < 3; ww++) {   // CNOT chain
                int cm = 8 >> ww, tm = 4 >> ww;
                cf tmp[16];
                #pragma unroll
                for (int i = 0; i < 16; i++) tmp[i] = st[(i & cm) ? (i ^ tm) : i];
                #pragma unroll
                for (int i = 0; i < 16; i++) st[i] = tmp[i];
            }
        }
        const int pm = __popc(j) & 3;          // bake in (-i)^popc(j)
        float2* uw = reinterpret_cast<float2*>(sUf4);
        const int jp = j >> 1, jl = j & 1;
        #pragma unroll
        for (int i = 0; i < 16; i++) {
            float r = st[i].re, im = st[i].im, nr, ni;
            if      (pm == 0) { nr =  r;  ni =  im; }
            else if (pm == 1) { nr =  im; ni = -r;  }
            else if (pm == 2) { nr = -r;  ni = -im; }
            else              { nr = -im; ni =  r;  }
            uw[(jp*16 + i)*2 + jl] = make_float2(nr, ni);
        }
    }
    __syncthreads();

    const float4 wrow = reinterpret_cast<const float4*>(W)[q];
    const float4 bv   = *reinterpret_cast<const float4*>(b);

    // z-lane roles (WHT output lanes)
    int zi = -1;
    if (q == 8) zi = 0; else if (q == 4) zi = 1;
    else if (q == 2) zi = 2; else if (q == 1) zi = 3;
    const bool zstore = (zi >= 0);

    float* poolW = sPool + w * (2*HOFF) + h * HOFF;
    const float* poolR = poolW + (6*(q>>2))*4 + (q & 3);

    float runS = 0.f, runQ = 0.f;

    for (; s2 < B; s2 += STRIDE) {
        // ---- fold staged rows into col-bin sums ----
        float c0 = A0.x+A0.y+A0.z+A0.w+A1.x+A1.y;
        float c1 = A1.z+A1.w+A2.x+A2.y+A2.z+A2.w;
        float c2 = A3.x+A3.y+A3.z+A3.w+A4.x+A4.y;
        float c3 = A4.z+A4.w+A5.x+A5.y+A5.z+A5.w;
        float t0 = B0.x+B0.y+B0.z+B0.w+B1.x+B1.y;
        float t1 = B1.z+B1.w+B2.x+B2.y+B2.z+B2.w;

        // ---- prefetch next pair (regs free now) ----
        if (s2 + STRIDE < B) ldall(s2 + STRIDE);

        // ---- transpose via smem ----
        *reinterpret_cast<float4*>(poolW + q*4) = make_float4(c0, c1, c2, c3);
        *reinterpret_cast<float2*>(poolW + rowB*4 + (q&1)*2) = make_float2(t0, t1);
        __syncwarp();

        // ---- pooled bin q: vertical sum of 6 rows ----
        float v = poolR[0] + poolR[4] + poolR[8] + poolR[12] + poolR[16] + poolR[20];
        v *= (1.0f / 36.0f);

        // ---- feats = pooled @ W + b (butterfly within 16-lane half) ----
        float f0 = v*wrow.x, f1 = v*wrow.y, f2 = v*wrow.z, f3 = v*wrow.w;
        #pragma unroll
        for (int m = 1; m < 16; m <<= 1) {
            f0 += __shfl_xor_sync(0xffffffffu, f0, m);
            f1 += __shfl_xor_sync(0xffffffffu, f1, m);
            f2 += __shfl_xor_sync(0xffffffffu, f2, m);
            f3 += __shfl_xor_sync(0xffffffffu, f3, m);
        }
        f0 += bv.x; f1 += bv.y; f2 += bv.z; f3 += bv.w;

        // ---- encoded product-state magnitudes ----
        float c0_,s_0,c1_,s_1,c2_,s_2,c3_,s_3;
        __sincosf(0.5f*f0, &s_0, &c0_);
        __sincosf(0.5f*f1, &s_1, &c1_);
        __sincosf(0.5f*f2, &s_2, &c2_);
        __sincosf(0.5f*f3, &s_3, &c3_);
        float w01v[4] = { c0_*c1_, c0_*s_1, s_0*c1_, s_0*s_1 };
        float w23v[4] = { c2_*c3_, c2_*s_3, s_2*c3_, s_2*s_3 };

        // ---- amp_q = sum_j U'[q][j] * m_j  (U' pre-rotated, from smem) ----
        float ar = 0.f, ai = 0.f;
        #pragma unroll
        for (int jp = 0; jp < 8; jp++) {
            float4 u = sUf4[jp*16 + q];
            float m0 = w01v[(2*jp) >> 2]   * w23v[(2*jp) & 3];
            float m1 = w01v[(2*jp+1) >> 2] * w23v[(2*jp+1) & 3];
            ar += u.x*m0 + u.z*m1;
            ai += u.y*m0 + u.w*m1;
        }
        float prob = ar*ar + ai*ai;

        // ---- expZ: Walsh-Hadamard butterfly over 16-lane half ----
        float v4 = prob;
        #pragma unroll
        for (int m = 1; m < 16; m <<= 1) {
            float o = __shfl_xor_sync(0xffffffffu, v4, m);
            v4 = (q & m) ? (o - v4) : (v4 + o);
        }

        // ---- z_w sits at lane q = 8>>w: store directly + accumulate stats ----
        if (zstore) {
            out[(s2 + h)*4 + zi] = v4;
            runS += v4;
            runQ += v4*v4;
        }
        __syncwarp();     // protect sPool reuse next iteration
    }

    // ---- stats: combine halves (xor-16 pairs z-lanes across halves) ----
    runS += __shfl_xor_sync(0xffffffffu, runS, 16);
    runQ += __shfl_xor_sync(0xffffffffu, runQ, 16);
    if (zstore && h == 0) {
        sPart[w][zi]     = runS;
        sPart[w][4 + zi] = runQ;
    }
    __syncthreads();

    if (tid < 8) {
        float t = 0.f;
        #pragma unroll
        for (int k = 0; k < WPB; k++) t += sPart[k][tid];
        g_part[bid * 8 + tid] = t;
    }
    __threadfence();
    if (tid == 0) sTicket = atomicAdd(&g_cnt, 1u);
    __syncthreads();

    if ((sTicket % GRID) == GRID - 1) {
        __threadfence();
        float* sRed = reinterpret_cast<float*>(sUf4);   // scratch (done with U)
        {
            int ch = tid & 7, row = tid >> 3;            // 32 rows x 8 channels
            float s = 0.f;
            for (int p2 = row; p2 < GRID; p2 += 32) s += __ldcg(&g_part[p2*8 + ch]);
            sRed[row*8 + ch] = s;
        }
        __syncthreads();
        if (tid < 8) {
            float tt = 0.f;
            #pragma unroll
            for (int r = 0; r < 32; r++) tt += sRed[r*8 + tid];
            sRed[256 + tid] = tt;
        }
        __syncthreads();
        if (tid < 4) {
            float invB = 1.0f / (float)B;
            float mu  = sRed[256 + tid] * invB;
            float var = sRed[260 + tid] * invB - mu*mu;    // biased var
            float scw = gamma[tid] * rsqrtf(var + 1e-5f);
            g_scale[tid]     = scw;
            g_scale[4 + tid] = beta[tid] - mu * scw;
        }
        __threadfence();
        __syncthreads();
        if (tid == 0) atomicAdd(&g_flag, 1u);
    }

    if (tid == 0) {
        while (*(volatile unsigned*)&g_flag == epoch) __nanosleep(64);
    }
    __syncthreads();
    __threadfence();

    if (tid < 8) sScale[tid] = *(volatile float*)&g_scale[tid];
    __syncthreads();

    // ---- normalize: one f4 per thread, coalesced ----
    {
        float4 scv = *reinterpret_cast<const float4*>(&sScale[0]);
        float4 shv = *reinterpret_cast<const float4*>(&sScale[4]);
        for (long i = (long)bid * 256 + tid; i < B; i += (long)GRID * 256) {
            float4 r = reinterpret_cast<float4*>(out)[i];
            r.x = r.x*scv.x + shv.x;
            r.y = r.y*scv.y + shv.y;
            r.z = r.z*scv.z + shv.z;
            r.w = r.w*scv.w + shv.w;
            reinterpret_cast<float4*>(out)[i] = r;
        }
    }
}

// ---------------- launch ----------------------------------------------------
extern "C" void kernel_launch(void* const* d_in, const int* in_sizes, int n_in,
                              void* d_out, int out_size)
{
    const float* x     = (const float*)d_in[0];  // [B,1,28,28]
    const float* W     = (const float*)d_in[1];  // [16,4]
    const float* b     = (const float*)d_in[2];  // [4]
    const float* vp    = (const float*)d_in[3];  // [3,4,3]
    const float* gamma = (const float*)d_in[4];  // [4]
    const float* beta  = (const float*)d_in[5];  // [4]
    float* out = (float*)d_out;                  // [B,4]

    int B = in_sizes[0] / 784;                   // 65536

    k_all<<<GRID, 256>>>(x, W, b, vp, gamma, beta, out, B);
}